// round 2
// baseline (speedup 1.0000x reference)
#include <cuda_runtime.h>
#include <mma.h>
#include <math.h>
#include <stdint.h>

using namespace nvcuda;

#define VV   50000
#define E    512
#define H    1024
#define B    256
#define S    256
#define G4H  4096   /* 4*H */

// ---------------- static device scratch (no cudaMalloc allowed) ----------------
__device__ float g_xproj_f[(size_t)S * B * G4H];   // 1 GB: x_t @ Wx_f  (layout [s][b][4H])
__device__ float g_xproj_b[(size_t)S * B * G4H];   // 1 GB: x_t @ Wx_b
__device__ float g_gates[2 * B * G4H];             // 8 MB: h @ Wh per step
__device__ float g_h[2 * B * H];                   // hidden state, fwd then bwd
__device__ float g_c[2 * B * H];                   // cell state

// ---------------- init ----------------
__global__ void zero_hc_kernel() {
    int i = blockIdx.x * blockDim.x + threadIdx.x;
    if (i < 2 * B * H) { g_h[i] = 0.f; g_c[i] = 0.f; }
}

// ---------------- xproj: gathered-embedding GEMM ----------------
// C[row, j] = sum_e emb[tok(row)][e] * Wx[e][j]   row = s*B + b, tf32 wmma
// block tile 64x128, BK=16, 256 threads (8 warps, 2x4 of 32x32 warp tiles)
__global__ void xproj_kernel(const int*   __restrict__ inputs,
                             const float* __restrict__ emb,
                             const float* __restrict__ Wx_f,
                             const float* __restrict__ Wx_b) {
    const int BK = 16;
    __shared__ __align__(128) float As[64][24];    // stride 24 floats = 96B (32B-mult)
    __shared__ __align__(128) float Bs[16][136];   // stride 136 floats = 544B (32B-mult)
    __shared__ int toks[64];

    const int ntile = blockIdx.x;            // 0..63 (cols over 2*4096)
    const int mtile = blockIdx.y;            // 0..1023
    const int dir   = ntile >> 5;            // 0 fwd, 1 bwd
    const int col0  = (ntile & 31) * 128;
    const int row0  = mtile * 64;
    const float* Wx = dir ? Wx_b : Wx_f;
    float* outp     = dir ? g_xproj_b : g_xproj_f;

    const int tid = threadIdx.x;
    if (tid < 64) {
        int row = row0 + tid;
        int s = row >> 8;          // row / B
        int b = row & 255;         // row % B
        toks[tid] = inputs[b * S + s];
    }
    __syncthreads();

    const int wid    = tid >> 5;
    const int warp_m = wid >> 2;   // 0..1
    const int warp_n = wid & 3;    // 0..3

    wmma::fragment<wmma::accumulator, 16, 16, 8, float> cfr[2][2];
#pragma unroll
    for (int i = 0; i < 2; i++)
#pragma unroll
        for (int j = 0; j < 2; j++) wmma::fill_fragment(cfr[i][j], 0.f);

    const int a_row = tid >> 2;            // 0..63
    const int a_col = (tid & 3) * 4;       // 0,4,8,12
    const int b_row = tid >> 4;            // 0..15
    const int b_col = (tid & 15) * 8;      // 0..120

    const size_t a_base = (size_t)toks[a_row] * E + a_col;

    for (int k0 = 0; k0 < E; k0 += BK) {
        float4 av = *(const float4*)(emb + a_base + k0);
        As[a_row][a_col + 0] = wmma::__float_to_tf32(av.x);
        As[a_row][a_col + 1] = wmma::__float_to_tf32(av.y);
        As[a_row][a_col + 2] = wmma::__float_to_tf32(av.z);
        As[a_row][a_col + 3] = wmma::__float_to_tf32(av.w);

        const float* bp = Wx + (size_t)(k0 + b_row) * G4H + col0 + b_col;
        float4 bv0 = *(const float4*)(bp);
        float4 bv1 = *(const float4*)(bp + 4);
        Bs[b_row][b_col + 0] = wmma::__float_to_tf32(bv0.x);
        Bs[b_row][b_col + 1] = wmma::__float_to_tf32(bv0.y);
        Bs[b_row][b_col + 2] = wmma::__float_to_tf32(bv0.z);
        Bs[b_row][b_col + 3] = wmma::__float_to_tf32(bv0.w);
        Bs[b_row][b_col + 4] = wmma::__float_to_tf32(bv1.x);
        Bs[b_row][b_col + 5] = wmma::__float_to_tf32(bv1.y);
        Bs[b_row][b_col + 6] = wmma::__float_to_tf32(bv1.z);
        Bs[b_row][b_col + 7] = wmma::__float_to_tf32(bv1.w);
        __syncthreads();

#pragma unroll
        for (int kf = 0; kf < 2; kf++) {
            wmma::fragment<wmma::matrix_a, 16, 16, 8, wmma::precision::tf32, wmma::row_major> afr[2];
            wmma::fragment<wmma::matrix_b, 16, 16, 8, wmma::precision::tf32, wmma::row_major> bfr[2];
#pragma unroll
            for (int i = 0; i < 2; i++)
                wmma::load_matrix_sync(afr[i], &As[warp_m * 32 + i * 16][kf * 8], 24);
#pragma unroll
            for (int j = 0; j < 2; j++)
                wmma::load_matrix_sync(bfr[j], &Bs[kf * 8][warp_n * 32 + j * 16], 136);
#pragma unroll
            for (int i = 0; i < 2; i++)
#pragma unroll
                for (int j = 0; j < 2; j++)
                    wmma::mma_sync(cfr[i][j], afr[i], bfr[j], cfr[i][j]);
        }
        __syncthreads();
    }

#pragma unroll
    for (int i = 0; i < 2; i++)
#pragma unroll
        for (int j = 0; j < 2; j++) {
            int r  = row0 + warp_m * 32 + i * 16;
            int cc = col0 + warp_n * 32 + j * 16;
            wmma::store_matrix_sync(outp + (size_t)r * G4H + cc, cfr[i][j], G4H,
                                    wmma::mem_row_major);
        }
}

// ---------------- recurrent GEMM: g_gates = g_h @ Wh (per direction) ----------------
__global__ void hgemm_kernel(const float* __restrict__ Wh_f,
                             const float* __restrict__ Wh_b) {
    const int BK = 16;
    __shared__ __align__(128) float As[64][24];
    __shared__ __align__(128) float Bs[16][136];

    const int ntile = blockIdx.x;            // 0..31
    const int mtile = blockIdx.y;            // 0..3
    const int dir   = blockIdx.z;            // 0..1
    const int col0  = ntile * 128;
    const int row0  = mtile * 64;
    const float* A  = g_h + (size_t)dir * B * H;       // [256][1024]
    const float* Wh = dir ? Wh_b : Wh_f;
    float* outp     = g_gates + (size_t)dir * B * G4H;

    const int tid = threadIdx.x;
    const int wid    = tid >> 5;
    const int warp_m = wid >> 2;
    const int warp_n = wid & 3;

    wmma::fragment<wmma::accumulator, 16, 16, 8, float> cfr[2][2];
#pragma unroll
    for (int i = 0; i < 2; i++)
#pragma unroll
        for (int j = 0; j < 2; j++) wmma::fill_fragment(cfr[i][j], 0.f);

    const int a_row = tid >> 2;
    const int a_col = (tid & 3) * 4;
    const int b_row = tid >> 4;
    const int b_col = (tid & 15) * 8;

    for (int k0 = 0; k0 < H; k0 += BK) {
        float4 av = *(const float4*)(A + (size_t)(row0 + a_row) * H + k0 + a_col);
        As[a_row][a_col + 0] = wmma::__float_to_tf32(av.x);
        As[a_row][a_col + 1] = wmma::__float_to_tf32(av.y);
        As[a_row][a_col + 2] = wmma::__float_to_tf32(av.z);
        As[a_row][a_col + 3] = wmma::__float_to_tf32(av.w);

        const float* bp = Wh + (size_t)(k0 + b_row) * G4H + col0 + b_col;
        float4 bv0 = *(const float4*)(bp);
        float4 bv1 = *(const float4*)(bp + 4);
        Bs[b_row][b_col + 0] = wmma::__float_to_tf32(bv0.x);
        Bs[b_row][b_col + 1] = wmma::__float_to_tf32(bv0.y);
        Bs[b_row][b_col + 2] = wmma::__float_to_tf32(bv0.z);
        Bs[b_row][b_col + 3] = wmma::__float_to_tf32(bv0.w);
        Bs[b_row][b_col + 4] = wmma::__float_to_tf32(bv1.x);
        Bs[b_row][b_col + 5] = wmma::__float_to_tf32(bv1.y);
        Bs[b_row][b_col + 6] = wmma::__float_to_tf32(bv1.z);
        Bs[b_row][b_col + 7] = wmma::__float_to_tf32(bv1.w);
        __syncthreads();

#pragma unroll
        for (int kf = 0; kf < 2; kf++) {
            wmma::fragment<wmma::matrix_a, 16, 16, 8, wmma::precision::tf32, wmma::row_major> afr[2];
            wmma::fragment<wmma::matrix_b, 16, 16, 8, wmma::precision::tf32, wmma::row_major> bfr[2];
#pragma unroll
            for (int i = 0; i < 2; i++)
                wmma::load_matrix_sync(afr[i], &As[warp_m * 32 + i * 16][kf * 8], 24);
#pragma unroll
            for (int j = 0; j < 2; j++)
                wmma::load_matrix_sync(bfr[j], &Bs[kf * 8][warp_n * 32 + j * 16], 136);
#pragma unroll
            for (int i = 0; i < 2; i++)
#pragma unroll
                for (int j = 0; j < 2; j++)
                    wmma::mma_sync(cfr[i][j], afr[i], bfr[j], cfr[i][j]);
        }
        __syncthreads();
    }

#pragma unroll
    for (int i = 0; i < 2; i++)
#pragma unroll
        for (int j = 0; j < 2; j++) {
            int r  = row0 + warp_m * 32 + i * 16;
            int cc = col0 + warp_n * 32 + j * 16;
            wmma::store_matrix_sync(outp + (size_t)r * G4H + cc, cfr[i][j], G4H,
                                    wmma::mem_row_major);
        }
}

// ---------------- LSTM cell elementwise ----------------
__device__ __forceinline__ float sigmoidf_(float x) { return 1.f / (1.f + expf(-x)); }

__global__ void cell_kernel(int t, const float* __restrict__ b_f,
                            const float* __restrict__ b_b) {
    int idx = blockIdx.x * blockDim.x + threadIdx.x;   // < 2*B*H = 524288
    int dir = idx >> 18;                                // /(B*H)
    int rem = idx & (B * H - 1);
    int b   = rem >> 10;
    int h   = rem & (H - 1);

    const float* g    = g_gates + (size_t)dir * B * G4H + (size_t)b * G4H;
    const float* bias = dir ? b_b : b_f;
    int sx = dir ? (S - 1 - t) : t;
    const float* xp = (dir ? g_xproj_b : g_xproj_f) + ((size_t)sx * B + b) * G4H;

    float gi = g[h]         + xp[h]         + bias[h];
    float gf = g[H + h]     + xp[H + h]     + bias[H + h];
    float go = g[2 * H + h] + xp[2 * H + h] + bias[2 * H + h];
    float gc = g[3 * H + h] + xp[3 * H + h] + bias[3 * H + h];

    float i_ = sigmoidf_(gi);
    float f_ = sigmoidf_(gf);
    float o_ = sigmoidf_(go);
    float ct = tanhf(gc);

    int hidx = dir * (B * H) + b * H + h;
    float c = f_ * g_c[hidx] + i_ * ct;
    g_c[hidx] = c;
    g_h[hidx] = o_ * tanhf(c);
}

// ---------------- head: (h_f + h_b) @ W_hq + b_q, softmax ----------------
__global__ void final_kernel(const float* __restrict__ W_hq,
                             const float* __restrict__ b_q,
                             float* __restrict__ out) {
    __shared__ float sm[256][10];
    int b   = blockIdx.x;
    int tid = threadIdx.x;

    float acc[10];
#pragma unroll
    for (int q = 0; q < 10; q++) acc[q] = 0.f;

    for (int h = tid; h < H; h += 256) {
        float hv = g_h[b * H + h] + g_h[B * H + b * H + h];
#pragma unroll
        for (int q = 0; q < 10; q++) acc[q] += hv * W_hq[h * 10 + q];
    }
#pragma unroll
    for (int q = 0; q < 10; q++) sm[tid][q] = acc[q];
    __syncthreads();

    for (int off = 128; off > 0; off >>= 1) {
        if (tid < off) {
#pragma unroll
            for (int q = 0; q < 10; q++) sm[tid][q] += sm[tid + off][q];
        }
        __syncthreads();
    }

    if (tid == 0) {
        float lg[10], mx = -1e30f;
#pragma unroll
        for (int q = 0; q < 10; q++) { lg[q] = sm[0][q] + b_q[q]; mx = fmaxf(mx, lg[q]); }
        float sum = 0.f;
#pragma unroll
        for (int q = 0; q < 10; q++) { lg[q] = expf(lg[q] - mx); sum += lg[q]; }
        float inv = 1.f / sum;
#pragma unroll
        for (int q = 0; q < 10; q++) out[b * 10 + q] = lg[q] * inv;
    }
}

// ---------------- launch ----------------
extern "C" void kernel_launch(void* const* d_in, const int* in_sizes, int n_in,
                              void* d_out, int out_size) {
    const int*   inputs = (const int*)  d_in[0];
    const float* emb    = (const float*)d_in[1];
    const float* Wx_f   = (const float*)d_in[2];
    const float* Wh_f   = (const float*)d_in[3];
    const float* b_f    = (const float*)d_in[4];
    const float* Wx_b   = (const float*)d_in[5];
    const float* Wh_b   = (const float*)d_in[6];
    const float* b_b    = (const float*)d_in[7];
    const float* W_hq   = (const float*)d_in[8];
    const float* b_q    = (const float*)d_in[9];
    float* out = (float*)d_out;

    zero_hc_kernel<<<2048, 256>>>();

    dim3 xg(64, 1024);
    xproj_kernel<<<xg, 256>>>(inputs, emb, Wx_f, Wx_b);

    dim3 hg(32, 4, 2);
    for (int t = 0; t < S; t++) {
        hgemm_kernel<<<hg, 256>>>(Wh_f, Wh_b);
        cell_kernel<<<2048, 256>>>(t, b_f, b_b);
    }

    final_kernel<<<256, 256>>>(W_hq, b_q, out);
}

// round 3
// speedup vs baseline: 1.0218x; 1.0218x over previous
#include <cuda_runtime.h>
#include <mma.h>
#include <math.h>
#include <stdint.h>

using namespace nvcuda;

#define E    512
#define H    1024
#define B    256
#define S    256
#define G4H  4096

// ---------------- static device scratch ----------------
__device__ float g_xproj[2][(size_t)S * B * G4H];   // permuted cols: p = 4h+g
__device__ float g_Whp[2][(size_t)H * G4H];         // permuted Wh
__device__ float g_Wxp[2][(size_t)E * G4H];         // permuted Wx
__device__ float g_biasp[2][G4H];                   // permuted bias
__device__ float g_h[2 * B * H];                    // rows: dir*256 + b
__device__ float g_c[2 * B * H];

// smem layout (floats): As[2][128][36] = 9216 | Bs[2][32][132] = 8448  -> 17664 floats
#define SMEM_FLOATS 17664
#define SMEM_BYTES  (SMEM_FLOATS * 4)
#define AS_OFF(buf, r, c) ((buf) * 4608 + (r) * 36 + (c))
#define BS_OFF(buf, r, c) (9216 + (buf) * 4224 + (r) * 132 + (c))

__device__ __forceinline__ void cp16(float* dst, const float* src) {
    unsigned sdst = (unsigned)__cvta_generic_to_shared(dst);
    asm volatile("cp.async.cg.shared.global [%0], [%1], 16;\n" :: "r"(sdst), "l"(src));
}
__device__ __forceinline__ void cp_commit() { asm volatile("cp.async.commit_group;\n"); }
template <int N>
__device__ __forceinline__ void cp_wait() { asm volatile("cp.async.wait_group %0;\n" :: "n"(N)); }

__device__ __forceinline__ float sigmoidf_(float x) { return 1.f / (1.f + expf(-x)); }

// ---------------- init ----------------
__global__ void zero_hc_kernel() {
    int i = blockIdx.x * blockDim.x + threadIdx.x;
    if (i < 2 * B * H) { g_h[i] = 0.f; g_c[i] = 0.f; }
}

// ---------------- one-time weight permutation: out col p=4h+g <- in col g*H+h ----------------
__global__ void prep_kernel(const float* __restrict__ Wh_f, const float* __restrict__ Wh_b,
                            const float* __restrict__ Wx_f, const float* __restrict__ Wx_b,
                            const float* __restrict__ b_f,  const float* __restrict__ b_b) {
    const long T1 = 2L * H * G4H;
    const long T2 = 2L * E * G4H;
    const long T3 = 2L * G4H;
    const long total = T1 + T2 + T3;
    for (long id = (long)blockIdx.x * blockDim.x + threadIdx.x; id < total;
         id += (long)gridDim.x * blockDim.x) {
        if (id < T1) {
            int dir = id >= (long)H * G4H;
            long o = id - (long)dir * H * G4H;
            int k = (int)(o / G4H), p = (int)(o % G4H);
            int h = p >> 2, g = p & 3;
            const float* src = dir ? Wh_b : Wh_f;
            g_Whp[dir][o] = src[(size_t)k * G4H + g * H + h];
        } else if (id < T1 + T2) {
            long o2 = id - T1;
            int dir = o2 >= (long)E * G4H;
            long o = o2 - (long)dir * E * G4H;
            int k = (int)(o / G4H), p = (int)(o % G4H);
            int h = p >> 2, g = p & 3;
            const float* src = dir ? Wx_b : Wx_f;
            g_Wxp[dir][o] = src[(size_t)k * G4H + g * H + h];
        } else {
            long o3 = id - T1 - T2;
            int dir = o3 >= G4H;
            int p = (int)(o3 - (long)dir * G4H);
            int h = p >> 2, g = p & 3;
            const float* src = dir ? b_b : b_f;
            g_biasp[dir][p] = src[g * H + h];
        }
    }
}

// ---------------- xproj: gathered-embedding GEMM (permuted Wx), 128x128 tile ----------------
__global__ void __launch_bounds__(256) xproj_kernel(const int* __restrict__ inputs,
                                                    const float* __restrict__ emb) {
    extern __shared__ float smem[];
    __shared__ int toks[128];
    const int tid   = threadIdx.x;
    const int ntile = blockIdx.x;      // 0..31
    const int mtile = blockIdx.y;      // 0..511
    const int dir   = blockIdx.z;      // 0..1
    const int col0  = ntile * 128;
    const int row0  = mtile * 128;
    const float* __restrict__ Bmat = g_Wxp[dir];

    if (tid < 128) {
        int row = row0 + tid;
        int s = row >> 8, b = row & 255;
        toks[tid] = inputs[b * S + s];
    }
    __syncthreads();

    const int wid    = tid >> 5;
    const int warp_m = wid >> 1;    // 0..3 (32 rows)
    const int warp_n = wid & 1;     // 0..1 (64 cols)

    wmma::fragment<wmma::accumulator, 16, 16, 8, float> acc[2][4];
#pragma unroll
    for (int i = 0; i < 2; i++)
#pragma unroll
        for (int j = 0; j < 4; j++) wmma::fill_fragment(acc[i][j], 0.f);

    auto loadAB = [&](int buf, int k0) {
#pragma unroll
        for (int i = 0; i < 4; i++) {
            int idx = tid + i * 256;
            int r = idx >> 3, c4 = idx & 7;       // A: 128 x 32
            cp16(&smem[AS_OFF(buf, r, c4 * 4)],
                 emb + (size_t)toks[r] * E + k0 + c4 * 4);
        }
#pragma unroll
        for (int i = 0; i < 4; i++) {
            int idx = tid + i * 256;
            int r = idx >> 5, c4 = idx & 31;      // B: 32 x 128
            cp16(&smem[BS_OFF(buf, r, c4 * 4)],
                 Bmat + (size_t)(k0 + r) * G4H + col0 + c4 * 4);
        }
    };

    loadAB(0, 0);
    cp_commit();
    const int NCHUNK = E / 32;   // 16
    for (int kc = 0; kc < NCHUNK; kc++) {
        int cur = kc & 1;
        if (kc + 1 < NCHUNK) { loadAB(cur ^ 1, (kc + 1) * 32); cp_commit(); cp_wait<1>(); }
        else cp_wait<0>();
        __syncthreads();
#pragma unroll
        for (int kf = 0; kf < 4; kf++) {
            wmma::fragment<wmma::matrix_a, 16, 16, 8, wmma::precision::tf32, wmma::row_major> af[2];
            wmma::fragment<wmma::matrix_b, 16, 16, 8, wmma::precision::tf32, wmma::row_major> bf[4];
#pragma unroll
            for (int i = 0; i < 2; i++)
                wmma::load_matrix_sync(af[i], &smem[AS_OFF(cur, warp_m * 32 + i * 16, kf * 8)], 36);
#pragma unroll
            for (int j = 0; j < 4; j++)
                wmma::load_matrix_sync(bf[j], &smem[BS_OFF(cur, kf * 8, warp_n * 64 + j * 16)], 132);
#pragma unroll
            for (int i = 0; i < 2; i++)
#pragma unroll
                for (int j = 0; j < 4; j++)
                    wmma::mma_sync(acc[i][j], af[i], bf[j], acc[i][j]);
        }
        __syncthreads();
    }

    float* outp = g_xproj[dir];
#pragma unroll
    for (int i = 0; i < 2; i++)
#pragma unroll
        for (int j = 0; j < 4; j++) {
            int r  = row0 + warp_m * 32 + i * 16;
            int cc = col0 + warp_n * 64 + j * 16;
            wmma::store_matrix_sync(outp + (size_t)r * G4H + cc, acc[i][j], G4H,
                                    wmma::mem_row_major);
        }
}

// ---------------- fused recurrent step: gates = h @ Whp ; cell epilogue ----------------
__global__ void __launch_bounds__(256) step_kernel(int t) {
    extern __shared__ float smem[];
    const int tid   = threadIdx.x;
    const int ntile = blockIdx.x;      // 0..31
    const int mtile = blockIdx.y;      // 0..3
    const int col0  = ntile * 128;
    const int row0  = mtile * 128;     // rows 0..255 fwd, 256..511 bwd
    const int dir   = mtile >> 1;
    const float* __restrict__ Bmat = g_Whp[dir];

    const int wid    = tid >> 5;
    const int warp_m = wid >> 1;
    const int warp_n = wid & 1;

    wmma::fragment<wmma::accumulator, 16, 16, 8, float> acc[2][4];
#pragma unroll
    for (int i = 0; i < 2; i++)
#pragma unroll
        for (int j = 0; j < 4; j++) wmma::fill_fragment(acc[i][j], 0.f);

    auto loadAB = [&](int buf, int k0) {
#pragma unroll
        for (int i = 0; i < 4; i++) {
            int idx = tid + i * 256;
            int r = idx >> 3, c4 = idx & 7;
            cp16(&smem[AS_OFF(buf, r, c4 * 4)],
                 g_h + (size_t)(row0 + r) * H + k0 + c4 * 4);
        }
#pragma unroll
        for (int i = 0; i < 4; i++) {
            int idx = tid + i * 256;
            int r = idx >> 5, c4 = idx & 31;
            cp16(&smem[BS_OFF(buf, r, c4 * 4)],
                 Bmat + (size_t)(k0 + r) * G4H + col0 + c4 * 4);
        }
    };

    loadAB(0, 0);
    cp_commit();
    const int NCHUNK = H / 32;   // 32
    for (int kc = 0; kc < NCHUNK; kc++) {
        int cur = kc & 1;
        if (kc + 1 < NCHUNK) { loadAB(cur ^ 1, (kc + 1) * 32); cp_commit(); cp_wait<1>(); }
        else cp_wait<0>();
        __syncthreads();
#pragma unroll
        for (int kf = 0; kf < 4; kf++) {
            wmma::fragment<wmma::matrix_a, 16, 16, 8, wmma::precision::tf32, wmma::row_major> af[2];
            wmma::fragment<wmma::matrix_b, 16, 16, 8, wmma::precision::tf32, wmma::row_major> bf[4];
#pragma unroll
            for (int i = 0; i < 2; i++)
                wmma::load_matrix_sync(af[i], &smem[AS_OFF(cur, warp_m * 32 + i * 16, kf * 8)], 36);
#pragma unroll
            for (int j = 0; j < 4; j++)
                wmma::load_matrix_sync(bf[j], &smem[BS_OFF(cur, kf * 8, warp_n * 64 + j * 16)], 132);
#pragma unroll
            for (int i = 0; i < 2; i++)
#pragma unroll
                for (int j = 0; j < 4; j++)
                    wmma::mma_sync(acc[i][j], af[i], bf[j], acc[i][j]);
        }
        __syncthreads();
    }

    // ---- epilogue: stage gate tile in smem (stride 132), then fused LSTM cell ----
#pragma unroll
    for (int i = 0; i < 2; i++)
#pragma unroll
        for (int j = 0; j < 4; j++)
            wmma::store_matrix_sync(&smem[(warp_m * 32 + i * 16) * 132 + warp_n * 64 + j * 16],
                                    acc[i][j], 132, wmma::mem_row_major);
    __syncthreads();

    const int sx = dir ? (S - 1 - t) : t;
    const float* __restrict__ xpbase = g_xproj[dir];
    const float* __restrict__ biasp  = g_biasp[dir];
#pragma unroll
    for (int u = tid; u < 128 * 32; u += 256) {
        int r   = u >> 5;          // local row 0..127
        int hl  = u & 31;          // local h 0..31
        int row = row0 + r;        // global row = dir*256 + b
        int b   = row & 255;
        int hg  = ntile * 32 + hl; // global h

        float4 gv = *(const float4*)&smem[r * 132 + hl * 4];
        float4 xv = *(const float4*)(xpbase + ((size_t)sx * B + b) * G4H + col0 + hl * 4);
        float4 bv = *(const float4*)(biasp + col0 + hl * 4);

        float i_ = sigmoidf_(gv.x + xv.x + bv.x);
        float f_ = sigmoidf_(gv.y + xv.y + bv.y);
        float o_ = sigmoidf_(gv.z + xv.z + bv.z);
        float ct = tanhf(gv.w + xv.w + bv.w);

        size_t hidx = (size_t)row * H + hg;
        float c = f_ * g_c[hidx] + i_ * ct;
        g_c[hidx] = c;
        g_h[hidx] = o_ * tanhf(c);
    }
}

// ---------------- head: (h_f + h_b) @ W_hq + b_q, softmax ----------------
__global__ void final_kernel(const float* __restrict__ W_hq,
                             const float* __restrict__ b_q,
                             float* __restrict__ out) {
    __shared__ float sm[256][10];
    int b   = blockIdx.x;
    int tid = threadIdx.x;

    float acc[10];
#pragma unroll
    for (int q = 0; q < 10; q++) acc[q] = 0.f;

    for (int h = tid; h < H; h += 256) {
        float hv = g_h[b * H + h] + g_h[B * H + b * H + h];
#pragma unroll
        for (int q = 0; q < 10; q++) acc[q] += hv * W_hq[h * 10 + q];
    }
#pragma unroll
    for (int q = 0; q < 10; q++) sm[tid][q] = acc[q];
    __syncthreads();

    for (int off = 128; off > 0; off >>= 1) {
        if (tid < off) {
#pragma unroll
            for (int q = 0; q < 10; q++) sm[tid][q] += sm[tid + off][q];
        }
        __syncthreads();
    }

    if (tid == 0) {
        float lg[10], mx = -1e30f;
#pragma unroll
        for (int q = 0; q < 10; q++) { lg[q] = sm[0][q] + b_q[q]; mx = fmaxf(mx, lg[q]); }
        float sum = 0.f;
#pragma unroll
        for (int q = 0; q < 10; q++) { lg[q] = expf(lg[q] - mx); sum += lg[q]; }
        float inv = 1.f / sum;
#pragma unroll
        for (int q = 0; q < 10; q++) out[b * 10 + q] = lg[q] * inv;
    }
}

// ---------------- launch ----------------
extern "C" void kernel_launch(void* const* d_in, const int* in_sizes, int n_in,
                              void* d_out, int out_size) {
    const int*   inputs = (const int*)  d_in[0];
    const float* emb    = (const float*)d_in[1];
    const float* Wx_f   = (const float*)d_in[2];
    const float* Wh_f   = (const float*)d_in[3];
    const float* b_f    = (const float*)d_in[4];
    const float* Wx_b   = (const float*)d_in[5];
    const float* Wh_b   = (const float*)d_in[6];
    const float* b_b    = (const float*)d_in[7];
    const float* W_hq   = (const float*)d_in[8];
    const float* b_q    = (const float*)d_in[9];
    float* out = (float*)d_out;

    cudaFuncSetAttribute(xproj_kernel, cudaFuncAttributeMaxDynamicSharedMemorySize, SMEM_BYTES);
    cudaFuncSetAttribute(step_kernel,  cudaFuncAttributeMaxDynamicSharedMemorySize, SMEM_BYTES);

    zero_hc_kernel<<<2048, 256>>>();
    prep_kernel<<<4096, 256>>>(Wh_f, Wh_b, Wx_f, Wx_b, b_f, b_b);

    xproj_kernel<<<dim3(32, 512, 2), 256, SMEM_BYTES>>>(inputs, emb);

    for (int t = 0; t < S; t++)
        step_kernel<<<dim3(32, 4), 256, SMEM_BYTES>>>(t);

    final_kernel<<<256, 256>>>(W_hq, b_q, out);
}

// round 7
// speedup vs baseline: 2.9135x; 2.8515x over previous
#include <cuda_runtime.h>
#include <cuda_fp16.h>
#include <mma.h>
#include <math.h>
#include <stdint.h>

using namespace nvcuda;

#define VV  50000
#define E   512
#define H   1024
#define B   256
#define S   256
#define G4H 4096

// ---------------- static device scratch ----------------
__device__ __align__(256) __half g_emb16[(size_t)VV * E];
__device__ __align__(256) __half g_WhT[2][(size_t)G4H * H];   // [p=4h+g][k]  (n-major)
__device__ __align__(256) __half g_WxT[2][(size_t)G4H * E];   // [p][e]       (n-major)
__device__ float g_biasp[2][G4H];
__device__ float g_xproj[2][(size_t)S * B * G4H];             // [s*B+b][p], bias folded in
__device__ __align__(256) __half g_h16[2 * B * H];            // rows: dir*256+b
__device__ float g_c[2 * B * H];

// smem (halfs): As[2][128][72] | Bs[2][128][72]  (B stored n-major: [n][k])
#define AS_OFF(buf, r, c) ((buf) * 9216 + (r) * 72 + (c))
#define BS_OFF(buf, r, c) (18432 + (buf) * 9216 + (r) * 72 + (c))
#define SMEM_HALFS 36864
#define SMEM_BYTES (SMEM_HALFS * 2)   // 73728 B (also covers 128x132 float gate stage)

__device__ __forceinline__ void cp16s(void* dst, const void* src) {
    unsigned d = (unsigned)__cvta_generic_to_shared(dst);
    asm volatile("cp.async.cg.shared.global [%0], [%1], 16;" :: "r"(d), "l"(src));
}
__device__ __forceinline__ void cpcommit() { asm volatile("cp.async.commit_group;"); }
template<int N> __device__ __forceinline__ void cpwait() { asm volatile("cp.async.wait_group %0;" :: "n"(N)); }

// ---------------- init ----------------
__global__ void zero_kernel() {
    int i = blockIdx.x * blockDim.x + threadIdx.x;
    if (i < 2 * B * H) { g_c[i] = 0.f; g_h16[i] = __float2half(0.f); }
}

// ---------------- one-time prep: fp16 convert + permute/transpose ----------------
__global__ void prep_kernel(const float* __restrict__ Wh_f, const float* __restrict__ Wh_b,
                            const float* __restrict__ Wx_f, const float* __restrict__ Wx_b,
                            const float* __restrict__ b_f,  const float* __restrict__ b_b,
                            const float* __restrict__ emb) {
    const long T0 = (long)VV * E;
    const long T1 = 2L * G4H * H;
    const long T2 = 2L * G4H * E;
    const long T3 = 2L * G4H;
    const long total = T0 + T1 + T2 + T3;
    for (long id = (long)blockIdx.x * blockDim.x + threadIdx.x; id < total;
         id += (long)gridDim.x * blockDim.x) {
        if (id < T0) {
            g_emb16[id] = __float2half(emb[id]);
        } else if (id < T0 + T1) {
            long o = id - T0;
            int dir = o >= (long)G4H * H;
            long oo = o - (long)dir * G4H * H;
            int p = (int)(oo / H), k = (int)(oo % H);
            int h = p >> 2, g = p & 3;
            const float* src = dir ? Wh_b : Wh_f;
            g_WhT[dir][oo] = __float2half(src[(size_t)k * G4H + g * H + h]);
        } else if (id < T0 + T1 + T2) {
            long o = id - T0 - T1;
            int dir = o >= (long)G4H * E;
            long oo = o - (long)dir * G4H * E;
            int p = (int)(oo / E), k = (int)(oo % E);
            int h = p >> 2, g = p & 3;
            const float* src = dir ? Wx_b : Wx_f;
            g_WxT[dir][oo] = __float2half(src[(size_t)k * G4H + g * H + h]);
        } else {
            long o = id - T0 - T1 - T2;
            int dir = o >= G4H;
            int p = (int)(o - (long)dir * G4H);
            int h = p >> 2, g = p & 3;
            const float* src = dir ? b_b : b_f;
            g_biasp[dir][p] = src[g * H + h];
        }
    }
}

// ---------------- shared GEMM core (fp16, 128x128 tile, BK=64) ----------------
// A rows from arow(r) pointer base (row-major, ld=K), B rows from Bsrc (n-major, ld=K)
// acc[2][4] per warp: warp_m = wid>>1 (32 rows), warp_n = wid&1 (64 cols)

#define GEMM_BODY(AROW_PTR, BROW_PTR, KDIM)                                              \
    const int wid    = tid >> 5;                                                         \
    const int warp_m = wid >> 1;                                                         \
    const int warp_n = wid & 1;                                                          \
    wmma::fragment<wmma::accumulator, 16, 16, 16, float> acc[2][4];                      \
    _Pragma("unroll") for (int i = 0; i < 2; i++)                                        \
        _Pragma("unroll") for (int j = 0; j < 4; j++) wmma::fill_fragment(acc[i][j], 0.f);\
    auto fill = [&](int buf, int k0) {                                                   \
        _Pragma("unroll") for (int i = 0; i < 4; i++) {                                  \
            int u = tid + i * 256;                                                       \
            int r = u >> 3, c8 = (u & 7) * 8;                                            \
            cp16s(&sh[AS_OFF(buf, r, c8)], (AROW_PTR) + k0 + c8);                        \
        }                                                                                \
        _Pragma("unroll") for (int i = 0; i < 4; i++) {                                  \
            int u = tid + i * 256;                                                       \
            int r = u >> 3, c8 = (u & 7) * 8;                                            \
            cp16s(&sh[BS_OFF(buf, r, c8)], (BROW_PTR) + k0 + c8);                        \
        }                                                                                \
    };                                                                                   \
    fill(0, 0); cpcommit();                                                              \
    const int NCHUNK = (KDIM) / 64;                                                      \
    for (int kc = 0; kc < NCHUNK; kc++) {                                                \
        int cur = kc & 1;                                                                \
        if (kc + 1 < NCHUNK) { fill(cur ^ 1, (kc + 1) * 64); cpcommit(); cpwait<1>(); }  \
        else cpwait<0>();                                                                \
        __syncthreads();                                                                 \
        _Pragma("unroll") for (int kf = 0; kf < 4; kf++) {                               \
            wmma::fragment<wmma::matrix_a, 16, 16, 16, __half, wmma::row_major> af[2];   \
            wmma::fragment<wmma::matrix_b, 16, 16, 16, __half, wmma::col_major> bf[4];   \
            _Pragma("unroll") for (int i = 0; i < 2; i++)                                \
                wmma::load_matrix_sync(af[i], &sh[AS_OFF(cur, warp_m * 32 + i * 16, kf * 16)], 72); \
            _Pragma("unroll") for (int j = 0; j < 4; j++)                                \
                wmma::load_matrix_sync(bf[j], &sh[BS_OFF(cur, warp_n * 64 + j * 16, kf * 16)], 72); \
            _Pragma("unroll") for (int i = 0; i < 2; i++)                                \
                _Pragma("unroll") for (int j = 0; j < 4; j++)                            \
                    wmma::mma_sync(acc[i][j], af[i], bf[j], acc[i][j]);                  \
        }                                                                                \
        __syncthreads();                                                                 \
    }                                                                                    \
    /* stage accumulators to smem row-major [128][132] floats */                          \
    float* sg = (float*)sh;                                                              \
    _Pragma("unroll") for (int i = 0; i < 2; i++)                                        \
        _Pragma("unroll") for (int j = 0; j < 4; j++)                                    \
            wmma::store_matrix_sync(&sg[(warp_m * 32 + i * 16) * 132 + warp_n * 64 + j * 16], \
                                    acc[i][j], 132, wmma::mem_row_major);                \
    __syncthreads();

// ---------------- xproj: D[row, p] = emb16[tok(row)] @ WxT^T + bias ----------------
__global__ void __launch_bounds__(256) xproj_kernel(const int* __restrict__ inputs) {
    extern __shared__ __align__(1024) __half sh[];
    __shared__ int toks[128];
    const int tid   = threadIdx.x;
    const int ntile = blockIdx.x;      // 0..31
    const int mtile = blockIdx.y;      // 0..511
    const int dir   = blockIdx.z;      // 0..1
    const int col0  = ntile * 128;
    const int row0  = mtile * 128;
    const __half* __restrict__ Bsrc = g_WxT[dir];

    if (tid < 128) {
        int row = row0 + tid;
        toks[tid] = inputs[(row & 255) * S + (row >> 8)];
    }
    __syncthreads();

    GEMM_BODY(g_emb16 + (size_t)toks[r] * E, Bsrc + (size_t)(col0 + r) * E, E)

    // coalesced writeback with bias
    float* __restrict__ outp = g_xproj[dir] + (size_t)row0 * G4H + col0;
    const float* __restrict__ bp = g_biasp[dir] + col0;
    for (int q = tid; q < 128 * 32; q += 256) {
        int r = q >> 5, hl = q & 31;
        float4 v = *(const float4*)&sg[r * 132 + hl * 4];
        float4 bb = *(const float4*)(bp + hl * 4);
        v.x += bb.x; v.y += bb.y; v.z += bb.z; v.w += bb.w;
        *(float4*)(outp + (size_t)r * G4H + hl * 4) = v;
    }
}

// ---------------- fused recurrent step: gates = h @ WhT^T ; LSTM cell ----------------
__global__ void __launch_bounds__(256) step_kernel(int t) {
    extern __shared__ __align__(1024) __half sh[];
    const int tid   = threadIdx.x;
    const int ntile = blockIdx.x;      // 0..31
    const int mtile = blockIdx.y;      // 0..3
    const int col0  = ntile * 128;
    const int row0  = mtile * 128;     // global rows: dir*256+b
    const int dir   = mtile >> 1;
    const __half* __restrict__ Bsrc = g_WhT[dir];

    GEMM_BODY(g_h16 + (size_t)(row0 + r) * H, Bsrc + (size_t)(col0 + r) * H, H)

    // fused LSTM cell (xproj already contains bias)
    const int sx = dir ? (S - 1 - t) : t;
    const int b0 = row0 & 255;
    const float* __restrict__ xpb = g_xproj[dir] + ((size_t)sx * B + b0) * G4H + col0;
    for (int q = tid; q < 128 * 32; q += 256) {
        int r  = q >> 5;
        int hl = q & 31;
        int grow = row0 + r;
        float4 gv = *(const float4*)&sg[r * 132 + hl * 4];
        float4 xv = *(const float4*)(xpb + (size_t)r * G4H + hl * 4);
        float i_ = 1.f / (1.f + expf(-(gv.x + xv.x)));
        float f_ = 1.f / (1.f + expf(-(gv.y + xv.y)));
        float o_ = 1.f / (1.f + expf(-(gv.z + xv.z)));
        float ct = tanhf(gv.w + xv.w);
        size_t ci = (size_t)grow * H + (col0 >> 2) + hl;   // h index = ntile*32 + hl
        float c = f_ * g_c[ci] + i_ * ct;
        g_c[ci] = c;
        g_h16[ci] = __float2half(o_ * tanhf(c));
    }
}

// ---------------- head: (h_f + h_b) @ W_hq + b_q, softmax ----------------
__global__ void final_kernel(const float* __restrict__ W_hq,
                             const float* __restrict__ b_q,
                             float* __restrict__ out) {
    __shared__ float sm[256][10];
    int b   = blockIdx.x;
    int tid = threadIdx.x;

    float acc[10];
#pragma unroll
    for (int q = 0; q < 10; q++) acc[q] = 0.f;

    for (int h = tid; h < H; h += 256) {
        float hv = __half2float(g_h16[b * H + h]) + __half2float(g_h16[(B + b) * H + h]);
#pragma unroll
        for (int q = 0; q < 10; q++) acc[q] += hv * W_hq[h * 10 + q];
    }
#pragma unroll
    for (int q = 0; q < 10; q++) sm[tid][q] = acc[q];
    __syncthreads();

    for (int off = 128; off > 0; off >>= 1) {
        if (tid < off) {
#pragma unroll
            for (int q = 0; q < 10; q++) sm[tid][q] += sm[tid + off][q];
        }
        __syncthreads();
    }

    if (tid == 0) {
        float lg[10], mx = -1e30f;
#pragma unroll
        for (int q = 0; q < 10; q++) { lg[q] = sm[0][q] + b_q[q]; mx = fmaxf(mx, lg[q]); }
        float sum = 0.f;
#pragma unroll
        for (int q = 0; q < 10; q++) { lg[q] = expf(lg[q] - mx); sum += lg[q]; }
        float inv = 1.f / sum;
#pragma unroll
        for (int q = 0; q < 10; q++) out[b * 10 + q] = lg[q] * inv;
    }
}

// ---------------- launch ----------------
extern "C" void kernel_launch(void* const* d_in, const int* in_sizes, int n_in,
                              void* d_out, int out_size) {
    const int*   inputs = (const int*)  d_in[0];
    const float* emb    = (const float*)d_in[1];
    const float* Wx_f   = (const float*)d_in[2];
    const float* Wh_f   = (const float*)d_in[3];
    const float* b_f    = (const float*)d_in[4];
    const float* Wx_b   = (const float*)d_in[5];
    const float* Wh_b   = (const float*)d_in[6];
    const float* b_b    = (const float*)d_in[7];
    const float* W_hq   = (const float*)d_in[8];
    const float* b_q    = (const float*)d_in[9];
    float* out = (float*)d_out;

    cudaFuncSetAttribute(xproj_kernel, cudaFuncAttributeMaxDynamicSharedMemorySize, SMEM_BYTES);
    cudaFuncSetAttribute(step_kernel,  cudaFuncAttributeMaxDynamicSharedMemorySize, SMEM_BYTES);

    zero_kernel<<<2048, 256>>>();
    prep_kernel<<<8192, 256>>>(Wh_f, Wh_b, Wx_f, Wx_b, b_f, b_b, emb);

    xproj_kernel<<<dim3(32, 512, 2), 256, SMEM_BYTES>>>(inputs);

    for (int t = 0; t < S; t++)
        step_kernel<<<dim3(32, 4), 256, SMEM_BYTES>>>(t);

    final_kernel<<<256, 256>>>(W_hq, b_q, out);
}

// round 9
// speedup vs baseline: 3.4134x; 1.1716x over previous
#include <cuda_runtime.h>
#include <cuda_fp16.h>
#include <mma.h>
#include <math.h>
#include <stdint.h>

using namespace nvcuda;

#define VV  50000
#define E   512
#define H   1024
#define B   256
#define S   256
#define G4H 4096

// ---------------- static device scratch ----------------
__device__ __align__(256) __half g_emb16[(size_t)VV * E];
__device__ __align__(256) __half g_WhT[2][(size_t)G4H * H];   // [p=4h+g][k]  (n-major)
__device__ __align__(256) __half g_WxT[2][(size_t)G4H * E];   // [p][e]       (n-major)
__device__ float g_biasp[2][G4H];
__device__ float g_xproj[2][(size_t)S * B * G4H];             // [s*B+b][p], bias folded in
__device__ __align__(256) __half g_h16[2 * B * H];            // rows: dir*256+b
__device__ float g_c[2 * B * H];

// smem (halfs): As[2][128][72] | Bs[2][128][72]  (B stored n-major: [n][k])
#define AS_OFF(buf, r, c) ((buf) * 9216 + (r) * 72 + (c))
#define BS_OFF(buf, r, c) (18432 + (buf) * 9216 + (r) * 72 + (c))
#define SMEM_HALFS 36864
#define SMEM_BYTES (SMEM_HALFS * 2)   // 73728 B (also covers 128x132 float gate stage)

__device__ __forceinline__ void cp16s(void* dst, const void* src) {
    unsigned d = (unsigned)__cvta_generic_to_shared(dst);
    asm volatile("cp.async.cg.shared.global [%0], [%1], 16;" :: "r"(d), "l"(src));
}
__device__ __forceinline__ void cpcommit() { asm volatile("cp.async.commit_group;"); }
template<int N> __device__ __forceinline__ void cpwait() { asm volatile("cp.async.wait_group %0;" :: "n"(N)); }

// ---------------- init ----------------
__global__ void zero_kernel() {
    int i = blockIdx.x * blockDim.x + threadIdx.x;
    if (i < 2 * B * H) { g_c[i] = 0.f; g_h16[i] = __float2half(0.f); }
}

// ---------------- one-time prep: fp16 convert + permute/transpose ----------------
__global__ void prep_kernel(const float* __restrict__ Wh_f, const float* __restrict__ Wh_b,
                            const float* __restrict__ Wx_f, const float* __restrict__ Wx_b,
                            const float* __restrict__ b_f,  const float* __restrict__ b_b,
                            const float* __restrict__ emb) {
    const long T0 = (long)VV * E;
    const long T1 = 2L * G4H * H;
    const long T2 = 2L * G4H * E;
    const long T3 = 2L * G4H;
    const long total = T0 + T1 + T2 + T3;
    for (long id = (long)blockIdx.x * blockDim.x + threadIdx.x; id < total;
         id += (long)gridDim.x * blockDim.x) {
        if (id < T0) {
            g_emb16[id] = __float2half(emb[id]);
        } else if (id < T0 + T1) {
            long o = id - T0;
            int dir = o >= (long)G4H * H;
            long oo = o - (long)dir * G4H * H;
            int p = (int)(oo / H), k = (int)(oo % H);
            int h = p >> 2, g = p & 3;
            const float* src = dir ? Wh_b : Wh_f;
            g_WhT[dir][oo] = __float2half(src[(size_t)k * G4H + g * H + h]);
        } else if (id < T0 + T1 + T2) {
            long o = id - T0 - T1;
            int dir = o >= (long)G4H * E;
            long oo = o - (long)dir * G4H * E;
            int p = (int)(oo / E), k = (int)(oo % E);
            int h = p >> 2, g = p & 3;
            const float* src = dir ? Wx_b : Wx_f;
            g_WxT[dir][oo] = __float2half(src[(size_t)k * G4H + g * H + h]);
        } else {
            long o = id - T0 - T1 - T2;
            int dir = o >= G4H;
            int p = (int)(o - (long)dir * G4H);
            int h = p >> 2, g = p & 3;
            const float* src = dir ? b_b : b_f;
            g_biasp[dir][p] = src[g * H + h];
        }
    }
}

// ---------------- shared GEMM core (fp16, 128x128 tile, BK=64, 512 thr / 16 warps) ----------------
// warp tile 32x32: warp_m = wid>>2 (0..3), warp_n = wid&3 (0..3), 2x2 frags

#define GEMM_BODY(AROW_PTR, BROW_PTR, KDIM)                                              \
    const int wid    = tid >> 5;                                                         \
    const int warp_m = wid >> 2;                                                         \
    const int warp_n = wid & 3;                                                          \
    wmma::fragment<wmma::accumulator, 16, 16, 16, float> acc[2][2];                      \
    _Pragma("unroll") for (int i = 0; i < 2; i++)                                        \
        _Pragma("unroll") for (int j = 0; j < 2; j++) wmma::fill_fragment(acc[i][j], 0.f);\
    auto fill = [&](int buf, int k0) {                                                   \
        _Pragma("unroll") for (int i = 0; i < 2; i++) {                                  \
            int u = tid + i * 512;                                                       \
            int r = u >> 3, c8 = (u & 7) * 8;                                            \
            cp16s(&sh[AS_OFF(buf, r, c8)], (AROW_PTR) + k0 + c8);                        \
        }                                                                                \
        _Pragma("unroll") for (int i = 0; i < 2; i++) {                                  \
            int u = tid + i * 512;                                                       \
            int r = u >> 3, c8 = (u & 7) * 8;                                            \
            cp16s(&sh[BS_OFF(buf, r, c8)], (BROW_PTR) + k0 + c8);                        \
        }                                                                                \
    };                                                                                   \
    fill(0, 0); cpcommit();                                                              \
    const int NCHUNK = (KDIM) / 64;                                                      \
    for (int kc = 0; kc < NCHUNK; kc++) {                                                \
        int cur = kc & 1;                                                                \
        if (kc + 1 < NCHUNK) { fill(cur ^ 1, (kc + 1) * 64); cpcommit(); cpwait<1>(); }  \
        else cpwait<0>();                                                                \
        __syncthreads();                                                                 \
        _Pragma("unroll") for (int kf = 0; kf < 4; kf++) {                               \
            wmma::fragment<wmma::matrix_a, 16, 16, 16, __half, wmma::row_major> af[2];   \
            wmma::fragment<wmma::matrix_b, 16, 16, 16, __half, wmma::col_major> bf[2];   \
            _Pragma("unroll") for (int i = 0; i < 2; i++)                                \
                wmma::load_matrix_sync(af[i], &sh[AS_OFF(cur, warp_m * 32 + i * 16, kf * 16)], 72); \
            _Pragma("unroll") for (int j = 0; j < 2; j++)                                \
                wmma::load_matrix_sync(bf[j], &sh[BS_OFF(cur, warp_n * 32 + j * 16, kf * 16)], 72); \
            _Pragma("unroll") for (int i = 0; i < 2; i++)                                \
                _Pragma("unroll") for (int j = 0; j < 2; j++)                            \
                    wmma::mma_sync(acc[i][j], af[i], bf[j], acc[i][j]);                  \
        }                                                                                \
        __syncthreads();                                                                 \
    }                                                                                    \
    /* stage accumulators to smem row-major [128][132] floats */                          \
    float* sg = (float*)sh;                                                              \
    _Pragma("unroll") for (int i = 0; i < 2; i++)                                        \
        _Pragma("unroll") for (int j = 0; j < 2; j++)                                    \
            wmma::store_matrix_sync(&sg[(warp_m * 32 + i * 16) * 132 + warp_n * 32 + j * 16], \
                                    acc[i][j], 132, wmma::mem_row_major);                \
    __syncthreads();

// ---------------- xproj: D[row, p] = emb16[tok(row)] @ WxT^T + bias ----------------
__global__ void __launch_bounds__(512) xproj_kernel(const int* __restrict__ inputs) {
    extern __shared__ __align__(1024) __half sh[];
    __shared__ int toks[128];
    const int tid   = threadIdx.x;
    const int ntile = blockIdx.x;      // 0..31
    const int mtile = blockIdx.y;      // 0..511
    const int dir   = blockIdx.z;      // 0..1
    const int col0  = ntile * 128;
    const int row0  = mtile * 128;
    const __half* __restrict__ Bsrc = g_WxT[dir];

    if (tid < 128) {
        int row = row0 + tid;
        toks[tid] = inputs[(row & 255) * S + (row >> 8)];
    }
    __syncthreads();

    GEMM_BODY(g_emb16 + (size_t)toks[r] * E, Bsrc + (size_t)(col0 + r) * E, E)

    // coalesced writeback with bias
    float* __restrict__ outp = g_xproj[dir] + (size_t)row0 * G4H + col0;
    const float* __restrict__ bp = g_biasp[dir] + col0;
    for (int q = tid; q < 128 * 32; q += 512) {
        int r = q >> 5, hl = q & 31;
        float4 v = *(const float4*)&sg[r * 132 + hl * 4];
        float4 bb = *(const float4*)(bp + hl * 4);
        v.x += bb.x; v.y += bb.y; v.z += bb.z; v.w += bb.w;
        *(float4*)(outp + (size_t)r * G4H + hl * 4) = v;
    }
}

// ---------------- fused recurrent step: gates = h @ WhT^T ; LSTM cell ----------------
__global__ void __launch_bounds__(512) step_kernel(int t) {
    extern __shared__ __align__(1024) __half sh[];
    const int tid   = threadIdx.x;
    const int ntile = blockIdx.x;      // 0..31
    const int mtile = blockIdx.y;      // 0..3
    const int col0  = ntile * 128;
    const int row0  = mtile * 128;     // global rows: dir*256+b
    const int dir   = mtile >> 1;
    const __half* __restrict__ Bsrc = g_WhT[dir];

    GEMM_BODY(g_h16 + (size_t)(row0 + r) * H, Bsrc + (size_t)(col0 + r) * H, H)

    // fused LSTM cell (xproj already contains bias)
    const int sx = dir ? (S - 1 - t) : t;
    const int b0 = row0 & 255;
    const float* __restrict__ xpb = g_xproj[dir] + ((size_t)sx * B + b0) * G4H + col0;
    for (int q = tid; q < 128 * 32; q += 512) {
        int r  = q >> 5;
        int hl = q & 31;
        int grow = row0 + r;
        float4 gv = *(const float4*)&sg[r * 132 + hl * 4];
        float4 xv = *(const float4*)(xpb + (size_t)r * G4H + hl * 4);
        float i_ = 1.f / (1.f + expf(-(gv.x + xv.x)));
        float f_ = 1.f / (1.f + expf(-(gv.y + xv.y)));
        float o_ = 1.f / (1.f + expf(-(gv.z + xv.z)));
        float ct = tanhf(gv.w + xv.w);
        size_t ci = (size_t)grow * H + (col0 >> 2) + hl;   // h index = ntile*32 + hl
        float c = f_ * g_c[ci] + i_ * ct;
        g_c[ci] = c;
        g_h16[ci] = __float2half(o_ * tanhf(c));
    }
}

// ---------------- head: (h_f + h_b) @ W_hq + b_q, softmax ----------------
__global__ void final_kernel(const float* __restrict__ W_hq,
                             const float* __restrict__ b_q,
                             float* __restrict__ out) {
    __shared__ float sm[256][10];
    int b   = blockIdx.x;
    int tid = threadIdx.x;

    float acc[10];
#pragma unroll
    for (int q = 0; q < 10; q++) acc[q] = 0.f;

    for (int h = tid; h < H; h += 256) {
        float hv = __half2float(g_h16[b * H + h]) + __half2float(g_h16[(B + b) * H + h]);
#pragma unroll
        for (int q = 0; q < 10; q++) acc[q] += hv * W_hq[h * 10 + q];
    }
#pragma unroll
    for (int q = 0; q < 10; q++) sm[tid][q] = acc[q];
    __syncthreads();

    for (int off = 128; off > 0; off >>= 1) {
        if (tid < off) {
#pragma unroll
            for (int q = 0; q < 10; q++) sm[tid][q] += sm[tid + off][q];
        }
        __syncthreads();
    }

    if (tid == 0) {
        float lg[10], mx = -1e30f;
#pragma unroll
        for (int q = 0; q < 10; q++) { lg[q] = sm[0][q] + b_q[q]; mx = fmaxf(mx, lg[q]); }
        float sum = 0.f;
#pragma unroll
        for (int q = 0; q < 10; q++) { lg[q] = expf(lg[q] - mx); sum += lg[q]; }
        float inv = 1.f / sum;
#pragma unroll
        for (int q = 0; q < 10; q++) out[b * 10 + q] = lg[q] * inv;
    }
}

// ---------------- launch ----------------
extern "C" void kernel_launch(void* const* d_in, const int* in_sizes, int n_in,
                              void* d_out, int out_size) {
    const int*   inputs = (const int*)  d_in[0];
    const float* emb    = (const float*)d_in[1];
    const float* Wx_f   = (const float*)d_in[2];
    const float* Wh_f   = (const float*)d_in[3];
    const float* b_f    = (const float*)d_in[4];
    const float* Wx_b   = (const float*)d_in[5];
    const float* Wh_b   = (const float*)d_in[6];
    const float* b_b    = (const float*)d_in[7];
    const float* W_hq   = (const float*)d_in[8];
    const float* b_q    = (const float*)d_in[9];
    float* out = (float*)d_out;

    cudaFuncSetAttribute(xproj_kernel, cudaFuncAttributeMaxDynamicSharedMemorySize, SMEM_BYTES);
    cudaFuncSetAttribute(step_kernel,  cudaFuncAttributeMaxDynamicSharedMemorySize, SMEM_BYTES);

    zero_kernel<<<2048, 256>>>();
    prep_kernel<<<8192, 256>>>(Wh_f, Wh_b, Wx_f, Wx_b, b_f, b_b, emb);

    xproj_kernel<<<dim3(32, 512, 2), 512, SMEM_BYTES>>>(inputs);

    for (int t = 0; t < S; t++)
        step_kernel<<<dim3(32, 4), 512, SMEM_BYTES>>>(t);

    final_kernel<<<256, 256>>>(W_hq, b_q, out);
}

// round 10
// speedup vs baseline: 4.0013x; 1.1722x over previous
#include <cuda_runtime.h>
#include <cuda_fp16.h>
#include <mma.h>
#include <math.h>
#include <stdint.h>

using namespace nvcuda;

#define VV  50000
#define E   512
#define H   1024
#define B   256
#define S   256
#define G4H 4096

// ---------------- static device scratch ----------------
__device__ __align__(256) __half g_emb16[(size_t)VV * E];
__device__ __align__(256) __half g_WhT[2][(size_t)G4H * H];   // [p=4h+g][k]  (n-major)
__device__ __align__(256) __half g_WxT[2][(size_t)G4H * E];   // [p][e]       (n-major)
__device__ float g_biasp[2][G4H];
__device__ float g_xproj[2][(size_t)S * B * G4H];             // [s*B+b][p], bias folded in
__device__ __align__(256) __half g_h16[2 * B * H];            // rows: dir*256+b
__device__ float g_c[2 * B * H];

__device__ __forceinline__ void cp16s(void* dst, const void* src) {
    unsigned d = (unsigned)__cvta_generic_to_shared(dst);
    asm volatile("cp.async.cg.shared.global [%0], [%1], 16;" :: "r"(d), "l"(src));
}
__device__ __forceinline__ void cpcommit() { asm volatile("cp.async.commit_group;"); }
template<int N> __device__ __forceinline__ void cpwait() { asm volatile("cp.async.wait_group %0;" :: "n"(N)); }

// ---------------- init ----------------
__global__ void zero_kernel() {
    int i = blockIdx.x * blockDim.x + threadIdx.x;
    if (i < 2 * B * H) { g_c[i] = 0.f; g_h16[i] = __float2half(0.f); }
}

// ---------------- one-time prep: fp16 convert + permute/transpose ----------------
__global__ void prep_kernel(const float* __restrict__ Wh_f, const float* __restrict__ Wh_b,
                            const float* __restrict__ Wx_f, const float* __restrict__ Wx_b,
                            const float* __restrict__ b_f,  const float* __restrict__ b_b,
                            const float* __restrict__ emb) {
    const long T0 = (long)VV * E;
    const long T1 = 2L * G4H * H;
    const long T2 = 2L * G4H * E;
    const long T3 = 2L * G4H;
    const long total = T0 + T1 + T2 + T3;
    for (long id = (long)blockIdx.x * blockDim.x + threadIdx.x; id < total;
         id += (long)gridDim.x * blockDim.x) {
        if (id < T0) {
            g_emb16[id] = __float2half(emb[id]);
        } else if (id < T0 + T1) {
            long o = id - T0;
            int dir = o >= (long)G4H * H;
            long oo = o - (long)dir * G4H * H;
            int p = (int)(oo / H), k = (int)(oo % H);
            int h = p >> 2, g = p & 3;
            const float* src = dir ? Wh_b : Wh_f;
            g_WhT[dir][oo] = __float2half(src[(size_t)k * G4H + g * H + h]);
        } else if (id < T0 + T1 + T2) {
            long o = id - T0 - T1;
            int dir = o >= (long)G4H * E;
            long oo = o - (long)dir * G4H * E;
            int p = (int)(oo / E), k = (int)(oo % E);
            int h = p >> 2, g = p & 3;
            const float* src = dir ? Wx_b : Wx_f;
            g_WxT[dir][oo] = __float2half(src[(size_t)k * G4H + g * H + h]);
        } else {
            long o = id - T0 - T1 - T2;
            int dir = o >= G4H;
            int p = (int)(o - (long)dir * G4H);
            int h = p >> 2, g = p & 3;
            const float* src = dir ? b_b : b_f;
            g_biasp[dir][p] = src[g * H + h];
        }
    }
}

// ================= xproj (2-stage, as R9) =================
#define XAS_OFF(buf, r, c) ((buf) * 9216 + (r) * 72 + (c))
#define XBS_OFF(buf, r, c) (18432 + (buf) * 9216 + (r) * 72 + (c))
#define XPROJ_SMEM (36864 * 2)

__global__ void __launch_bounds__(512) xproj_kernel(const int* __restrict__ inputs) {
    extern __shared__ __align__(1024) __half sh[];
    __shared__ int toks[128];
    const int tid   = threadIdx.x;
    const int ntile = blockIdx.x;
    const int mtile = blockIdx.y;
    const int dir   = blockIdx.z;
    const int col0  = ntile * 128;
    const int row0  = mtile * 128;
    const __half* __restrict__ Bsrc = g_WxT[dir];

    if (tid < 128) {
        int row = row0 + tid;
        toks[tid] = inputs[(row & 255) * S + (row >> 8)];
    }
    __syncthreads();

    const int wid    = tid >> 5;
    const int warp_m = wid >> 2;
    const int warp_n = wid & 3;
    wmma::fragment<wmma::accumulator, 16, 16, 16, float> acc[2][2];
#pragma unroll
    for (int i = 0; i < 2; i++)
#pragma unroll
        for (int j = 0; j < 2; j++) wmma::fill_fragment(acc[i][j], 0.f);

    auto fill = [&](int buf, int k0) {
#pragma unroll
        for (int i = 0; i < 2; i++) {
            int u = tid + i * 512;
            int r = u >> 3, c8 = (u & 7) * 8;
            cp16s(&sh[XAS_OFF(buf, r, c8)], g_emb16 + (size_t)toks[r] * E + k0 + c8);
        }
#pragma unroll
        for (int i = 0; i < 2; i++) {
            int u = tid + i * 512;
            int r = u >> 3, c8 = (u & 7) * 8;
            cp16s(&sh[XBS_OFF(buf, r, c8)], Bsrc + (size_t)(col0 + r) * E + k0 + c8);
        }
    };
    fill(0, 0); cpcommit();
    const int NCHUNK = E / 64;
    for (int kc = 0; kc < NCHUNK; kc++) {
        int cur = kc & 1;
        if (kc + 1 < NCHUNK) { fill(cur ^ 1, (kc + 1) * 64); cpcommit(); cpwait<1>(); }
        else cpwait<0>();
        __syncthreads();
#pragma unroll
        for (int kf = 0; kf < 4; kf++) {
            wmma::fragment<wmma::matrix_a, 16, 16, 16, __half, wmma::row_major> af[2];
            wmma::fragment<wmma::matrix_b, 16, 16, 16, __half, wmma::col_major> bf[2];
#pragma unroll
            for (int i = 0; i < 2; i++)
                wmma::load_matrix_sync(af[i], &sh[XAS_OFF(cur, warp_m * 32 + i * 16, kf * 16)], 72);
#pragma unroll
            for (int j = 0; j < 2; j++)
                wmma::load_matrix_sync(bf[j], &sh[XBS_OFF(cur, warp_n * 32 + j * 16, kf * 16)], 72);
#pragma unroll
            for (int i = 0; i < 2; i++)
#pragma unroll
                for (int j = 0; j < 2; j++)
                    wmma::mma_sync(acc[i][j], af[i], bf[j], acc[i][j]);
        }
        __syncthreads();
    }
    float* sg = (float*)sh;
#pragma unroll
    for (int i = 0; i < 2; i++)
#pragma unroll
        for (int j = 0; j < 2; j++)
            wmma::store_matrix_sync(&sg[(warp_m * 32 + i * 16) * 132 + warp_n * 32 + j * 16],
                                    acc[i][j], 132, wmma::mem_row_major);
    __syncthreads();

    float* __restrict__ outp = g_xproj[dir] + (size_t)row0 * G4H + col0;
    const float* __restrict__ bp = g_biasp[dir] + col0;
    for (int q = tid; q < 128 * 32; q += 512) {
        int r = q >> 5, hl = q & 31;
        float4 v = *(const float4*)&sg[r * 132 + hl * 4];
        float4 bb = *(const float4*)(bp + hl * 4);
        v.x += bb.x; v.y += bb.y; v.z += bb.z; v.w += bb.w;
        *(float4*)(outp + (size_t)r * G4H + hl * 4) = v;
    }
}

// ================= step kernel: 3-stage pipeline + epilogue prefetch =================
// smem (halfs): 3 stages x (A 128x72 | B 128x72) = 55296 halfs (110592 B)
// then xp_s: 128x128 floats (65536 B) @ float idx 27648
// then c_s : 128x32  floats (16384 B) @ float idx 44032
#define SAS_OFF(buf, r, c) ((buf) * 18432 + (r) * 72 + (c))
#define SBS_OFF(buf, r, c) ((buf) * 18432 + 9216 + (r) * 72 + (c))
#define XP_F 27648
#define C_F  44032
#define STEP_SMEM 192512

__global__ void __launch_bounds__(512) step_kernel(int t) {
    extern __shared__ __align__(1024) __half sh[];
    float* shf = (float*)sh;
    const int tid   = threadIdx.x;
    const int ntile = blockIdx.x;      // 0..31
    const int mtile = blockIdx.y;      // 0..3
    const int col0  = ntile * 128;
    const int row0  = mtile * 128;     // global rows: dir*256+b
    const int dir   = mtile >> 1;
    const __half* __restrict__ Bsrc = g_WhT[dir];

    const int wid    = tid >> 5;
    const int warp_m = wid >> 2;
    const int warp_n = wid & 3;

    wmma::fragment<wmma::accumulator, 16, 16, 16, float> acc[2][2];
#pragma unroll
    for (int i = 0; i < 2; i++)
#pragma unroll
        for (int j = 0; j < 2; j++) wmma::fill_fragment(acc[i][j], 0.f);

    auto fill = [&](int buf, int k0) {
#pragma unroll
        for (int i = 0; i < 2; i++) {
            int u = tid + i * 512;
            int r = u >> 3, c8 = (u & 7) * 8;
            cp16s(&sh[SAS_OFF(buf, r, c8)], g_h16 + (size_t)(row0 + r) * H + k0 + c8);
        }
#pragma unroll
        for (int i = 0; i < 2; i++) {
            int u = tid + i * 512;
            int r = u >> 3, c8 = (u & 7) * 8;
            cp16s(&sh[SBS_OFF(buf, r, c8)], Bsrc + (size_t)(col0 + r) * H + k0 + c8);
        }
    };

    // F0, F1, then epilogue prefetch P (xproj slice + c slice)
    fill(0, 0);  cpcommit();
    fill(1, 64); cpcommit();
    {
        const int sx = dir ? (S - 1 - t) : t;
        const int b0 = row0 & 255;
        const float* __restrict__ xpb = g_xproj[dir] + ((size_t)sx * B + b0) * G4H + col0;
#pragma unroll
        for (int i = 0; i < 8; i++) {           // 4096 float4s
            int u = tid + i * 512;
            int r = u >> 5, c4 = u & 31;
            cp16s(&shf[XP_F + r * 128 + c4 * 4], xpb + (size_t)r * G4H + c4 * 4);
        }
        const float* __restrict__ cb = g_c + (size_t)row0 * H + ntile * 32;
#pragma unroll
        for (int i = 0; i < 2; i++) {           // 1024 float4s
            int u = tid + i * 512;
            int r = u >> 3, c4 = u & 7;
            cp16s(&shf[C_F + r * 32 + c4 * 4], cb + (size_t)r * H + c4 * 4);
        }
        cpcommit();
    }

    const int NCHUNK = H / 64;   // 16
    for (int kc = 0; kc < NCHUNK; kc++) {
        if (kc < 2) cpwait<2>();
        else if (kc + 1 < NCHUNK) cpwait<1>();
        else cpwait<0>();
        __syncthreads();
        if (kc + 2 < NCHUNK) { fill((kc + 2) % 3, (kc + 2) * 64); cpcommit(); }
        const int cur = kc % 3;
#pragma unroll
        for (int kf = 0; kf < 4; kf++) {
            wmma::fragment<wmma::matrix_a, 16, 16, 16, __half, wmma::row_major> af[2];
            wmma::fragment<wmma::matrix_b, 16, 16, 16, __half, wmma::col_major> bf[2];
#pragma unroll
            for (int i = 0; i < 2; i++)
                wmma::load_matrix_sync(af[i], &sh[SAS_OFF(cur, warp_m * 32 + i * 16, kf * 16)], 72);
#pragma unroll
            for (int j = 0; j < 2; j++)
                wmma::load_matrix_sync(bf[j], &sh[SBS_OFF(cur, warp_n * 32 + j * 16, kf * 16)], 72);
#pragma unroll
            for (int i = 0; i < 2; i++)
#pragma unroll
                for (int j = 0; j < 2; j++)
                    wmma::mma_sync(acc[i][j], af[i], bf[j], acc[i][j]);
        }
    }
    __syncthreads();

    // stage gates into stage region as float [128][132]
    float* sg = shf;
#pragma unroll
    for (int i = 0; i < 2; i++)
#pragma unroll
        for (int j = 0; j < 2; j++)
            wmma::store_matrix_sync(&sg[(warp_m * 32 + i * 16) * 132 + warp_n * 32 + j * 16],
                                    acc[i][j], 132, wmma::mem_row_major);
    __syncthreads();

    // fused LSTM cell, all operands in smem
    for (int q = tid; q < 128 * 32; q += 512) {
        int r  = q >> 5;
        int hl = q & 31;
        int grow = row0 + r;
        float4 gv = *(const float4*)&sg[r * 132 + hl * 4];
        float4 xv = *(const float4*)&shf[XP_F + r * 128 + hl * 4];
        float cprev = shf[C_F + r * 32 + hl];
        float i_ = 1.f / (1.f + expf(-(gv.x + xv.x)));
        float f_ = 1.f / (1.f + expf(-(gv.y + xv.y)));
        float o_ = 1.f / (1.f + expf(-(gv.z + xv.z)));
        float ct = tanhf(gv.w + xv.w);
        size_t ci = (size_t)grow * H + (col0 >> 2) + hl;   // h index = ntile*32 + hl
        float c = f_ * cprev + i_ * ct;
        g_c[ci] = c;
        g_h16[ci] = __float2half(o_ * tanhf(c));
    }
}

// ---------------- head: (h_f + h_b) @ W_hq + b_q, softmax ----------------
__global__ void final_kernel(const float* __restrict__ W_hq,
                             const float* __restrict__ b_q,
                             float* __restrict__ out) {
    __shared__ float sm[256][10];
    int b   = blockIdx.x;
    int tid = threadIdx.x;

    float acc[10];
#pragma unroll
    for (int q = 0; q < 10; q++) acc[q] = 0.f;

    for (int h = tid; h < H; h += 256) {
        float hv = __half2float(g_h16[b * H + h]) + __half2float(g_h16[(B + b) * H + h]);
#pragma unroll
        for (int q = 0; q < 10; q++) acc[q] += hv * W_hq[h * 10 + q];
    }
#pragma unroll
    for (int q = 0; q < 10; q++) sm[tid][q] = acc[q];
    __syncthreads();

    for (int off = 128; off > 0; off >>= 1) {
        if (tid < off) {
#pragma unroll
            for (int q = 0; q < 10; q++) sm[tid][q] += sm[tid + off][q];
        }
        __syncthreads();
    }

    if (tid == 0) {
        float lg[10], mx = -1e30f;
#pragma unroll
        for (int q = 0; q < 10; q++) { lg[q] = sm[0][q] + b_q[q]; mx = fmaxf(mx, lg[q]); }
        float sum = 0.f;
#pragma unroll
        for (int q = 0; q < 10; q++) { lg[q] = expf(lg[q] - mx); sum += lg[q]; }
        float inv = 1.f / sum;
#pragma unroll
        for (int q = 0; q < 10; q++) out[b * 10 + q] = lg[q] * inv;
    }
}

// ---------------- launch ----------------
extern "C" void kernel_launch(void* const* d_in, const int* in_sizes, int n_in,
                              void* d_out, int out_size) {
    const int*   inputs = (const int*)  d_in[0];
    const float* emb    = (const float*)d_in[1];
    const float* Wx_f   = (const float*)d_in[2];
    const float* Wh_f   = (const float*)d_in[3];
    const float* b_f    = (const float*)d_in[4];
    const float* Wx_b   = (const float*)d_in[5];
    const float* Wh_b   = (const float*)d_in[6];
    const float* b_b    = (const float*)d_in[7];
    const float* W_hq   = (const float*)d_in[8];
    const float* b_q    = (const float*)d_in[9];
    float* out = (float*)d_out;

    cudaFuncSetAttribute(xproj_kernel, cudaFuncAttributeMaxDynamicSharedMemorySize, XPROJ_SMEM);
    cudaFuncSetAttribute(step_kernel,  cudaFuncAttributeMaxDynamicSharedMemorySize, STEP_SMEM);

    zero_kernel<<<2048, 256>>>();
    prep_kernel<<<8192, 256>>>(Wh_f, Wh_b, Wx_f, Wx_b, b_f, b_b, emb);

    xproj_kernel<<<dim3(32, 512, 2), 512, XPROJ_SMEM>>>(inputs);

    for (int t = 0; t < S; t++)
        step_kernel<<<dim3(32, 4), 512, STEP_SMEM>>>(t);

    final_kernel<<<256, 256>>>(W_hq, b_q, out);
}